// round 17
// baseline (speedup 1.0000x reference)
#include <cuda_runtime.h>

#define NJ 24
#define BB 32                 // bodies per tile (= threads per block)
#define T  32
#define PSTR 19               // pos stride per body in float4 (76 words: conflict-free)

#define CP_ASYNC16(dst, src) \
    asm volatile("cp.async.cg.shared.global [%0], [%1], 16;" :: "r"(dst), "l"(src) : "memory")
#define CP_COMMIT()  asm volatile("cp.async.commit_group;" ::: "memory")
#define CP_WAIT0()   asm volatile("cp.async.wait_group 0;" ::: "memory")

__device__ __forceinline__ unsigned s2u(const void* p) {
    return (unsigned)__cvta_generic_to_shared(p);
}

__global__ __launch_bounds__(T, 10)
void fk_kernel(const float4* __restrict__ rot4,   // [nB*24] quats (w,x,y,z)
               const float4* __restrict__ pos4,   // [nB*18] packed positions
               float4*       __restrict__ out4,   // [nB*18] packed output
               int numTiles, int nB)
{
    __shared__ float4 qs[NJ * BB];      // 12288 B, transposed + xor-swizzled
    __shared__ float4 pd[BB * PSTR];    //  9728 B, raw per-body, padded stride

    const int t = threadIdx.x;
    const int stride = gridDim.x;
    constexpr int PAR[NJ] = {-1,0,0,0,1,2,3,4,5,6,7,8,9,9,9,12,13,14,16,17,18,19,20,21};

    // ---- coalesced cp.async stagers ----
    auto loadQuats = [&](int tile) {
        const float4* qsrc = rot4 + (size_t)tile * (BB * NJ);
#pragma unroll
        for (int k = 0; k < NJ; ++k) {             // 768 quat float4 / 32 thr
            const int base = k * T;                // compile-time
            int u = (base % NJ) + t;               // < 56
            int a = (u >= NJ) + (u >= 2 * NJ);
            int j    = u - a * NJ;                 // base+t == body*24 + j
            int body = base / NJ + a;
            CP_ASYNC16(s2u(qs + (j * BB + (body ^ j))), qsrc + (base + t));
        }
    };
    auto loadPos = [&](int tile) {
        const float4* psrc = pos4 + (size_t)tile * (BB * 18);
#pragma unroll
        for (int k = 0; k < 18; ++k) {             // 576 pos float4 / 32 thr
            const int base = k * T;
            int u = (base % 18) + t;               // < 50
            int a = (u >= 18) + (u >= 36);
            int kk   = u - a * 18;                 // base+t == body*18 + kk
            int body = base / 18 + a;
            CP_ASYNC16(s2u(pd + (body * PSTR + kk)), psrc + (base + t));
        }
    };

    if (blockIdx.x < (unsigned)numTiles) {
        loadQuats(blockIdx.x);
        loadPos(blockIdx.x);
        CP_COMMIT();

        for (int tile = blockIdx.x; tile < numTiles; tile += stride) {
            const int  next    = tile + stride;
            const bool hasNext = next < numTiles;

            CP_WAIT0();
            __syncwarp();

            // ---- compute: thread t owns body t; chained quaternions ----
            float Qw[NJ], Qx[NJ], Qy[NJ], Qz[NJ];
            float Gx[NJ], Gy[NJ], Gz[NJ];
            float pl[12];                          // 4 joints' local positions
            float gl[12];                          // 4 joints' global positions

#pragma unroll
            for (int j = 0; j < NJ; ++j) {
                if ((j & 3) == 0) {                // 3x LDS.128 -> 4 joints' positions
                    const int g = j >> 2;
#pragma unroll
                    for (int m = 0; m < 3; ++m) {
                        float4 v = pd[t * PSTR + 3 * g + m];
                        pl[4*m+0] = v.x; pl[4*m+1] = v.y; pl[4*m+2] = v.z; pl[4*m+3] = v.w;
                    }
                }
                float4 q = qs[j * BB + (t ^ j)];
                float w = q.x, x = q.y, y = q.z, z = q.w;
                float inv = rsqrtf(w*w + x*x + y*y + z*z);
                w *= inv; x *= inv; y *= inv; z *= inv;

                const int d3 = 3 * (j & 3);        // slot within pl/gl (0,3,6,9)
                float t0 = pl[d3+0], t1 = pl[d3+1], t2 = pl[d3+2];

                const int pa = PAR[j];
                if (pa < 0) {
                    Qw[j] = w; Qx[j] = x; Qy[j] = y; Qz[j] = z;
                    Gx[j] = t0; Gy[j] = t1; Gz[j] = t2;
                } else {
                    float pw = Qw[pa], px = Qx[pa], py = Qy[pa], pz = Qz[pa];
                    // global quat = parent ⊗ local
                    Qw[j] = pw*w - px*x - py*y - pz*z;
                    Qx[j] = pw*x + px*w + py*z - pz*y;
                    Qy[j] = pw*y - px*z + py*w + pz*x;
                    Qz[j] = pw*z + px*y - py*x + pz*w;
                    // v' = v + 2*pv×(pv×v + pw*v)
                    float ux = py*t2 - pz*t1 + pw*t0;
                    float uy = pz*t0 - px*t2 + pw*t1;
                    float uz = px*t1 - py*t0 + pw*t2;
                    float cx = py*uz - pz*uy;
                    float cy = pz*ux - px*uz;
                    float cz = px*uy - py*ux;
                    Gx[j] = Gx[pa] + t0 + 2.0f*cx;
                    Gy[j] = Gy[pa] + t1 + 2.0f*cy;
                    Gz[j] = Gz[pa] + t2 + 2.0f*cz;
                }
                gl[d3+0] = Gx[j];
                gl[d3+1] = Gy[j];
                gl[d3+2] = Gz[j];
                if ((j & 3) == 3) {                // overwrite consumed pos slots
                    const int g = j >> 2;
#pragma unroll
                    for (int m = 0; m < 3; ++m)
                        pd[t * PSTR + 3 * g + m] =
                            make_float4(gl[4*m+0], gl[4*m+1], gl[4*m+2], gl[4*m+3]);
                }
            }
            __syncwarp();                          // all qs reads done (lockstep + fence)

            // ---- qs is dead: start next tile's quat loads NOW (overlap writeout) ----
            if (hasNext) { loadQuats(next); CP_COMMIT(); }

            // ---- writeout: LDS.128 from pd -> coalesced STG.128 ----
            float4* dst = out4 + (size_t)tile * (BB * 18);
#pragma unroll
            for (int k = 0; k < 18; ++k) {
                const int base = k * T;
                int u = (base % 18) + t;
                int a = (u >= 18) + (u >= 36);
                int kk   = u - a * 18;
                int body = base / 18 + a;
                dst[base + t] = pd[body * PSTR + kk];
            }
            __syncwarp();                          // pd reads done

            // ---- pd is dead: next tile's pos loads ----
            if (hasNext) { loadPos(next); CP_COMMIT(); }
        }
        CP_WAIT0();
    }

    // ---- remainder bodies (nB % 32 != 0; never taken for B=131072) ----
    const int rem = nB - numTiles * BB;
    if (rem > 0 && blockIdx.x == 0) {
        long long b = (long long)numTiles * BB + t;
        if (b < nB) {
            const float4* q4 = rot4 + b * NJ;
            const float*  p  = (const float*)(pos4) + b * 72;
            float*        o  = (float*)(out4) + b * 72;
            float Qw[NJ], Qx[NJ], Qy[NJ], Qz[NJ], Gx[NJ], Gy[NJ], Gz[NJ];
#pragma unroll
            for (int j = 0; j < NJ; ++j) {
                float4 q = q4[j];
                float w = q.x, x = q.y, y = q.z, z = q.w;
                float inv = rsqrtf(w*w + x*x + y*y + z*z);
                w *= inv; x *= inv; y *= inv; z *= inv;
                float t0 = p[3*j+0], t1 = p[3*j+1], t2 = p[3*j+2];
                const int pa = PAR[j];
                if (pa < 0) {
                    Qw[j] = w; Qx[j] = x; Qy[j] = y; Qz[j] = z;
                    Gx[j] = t0; Gy[j] = t1; Gz[j] = t2;
                } else {
                    float pw = Qw[pa], px = Qx[pa], py = Qy[pa], pz = Qz[pa];
                    Qw[j] = pw*w - px*x - py*y - pz*z;
                    Qx[j] = pw*x + px*w + py*z - pz*y;
                    Qy[j] = pw*y - px*z + py*w + pz*x;
                    Qz[j] = pw*z + px*y - py*x + pz*w;
                    float ux = py*t2 - pz*t1 + pw*t0;
                    float uy = pz*t0 - px*t2 + pw*t1;
                    float uz = px*t1 - py*t0 + pw*t2;
                    float cx = py*uz - pz*uy;
                    float cy = pz*ux - px*uz;
                    float cz = px*uy - py*ux;
                    Gx[j] = Gx[pa] + t0 + 2.0f*cx;
                    Gy[j] = Gy[pa] + t1 + 2.0f*cy;
                    Gz[j] = Gz[pa] + t2 + 2.0f*cz;
                }
                o[3*j+0] = Gx[j]; o[3*j+1] = Gy[j]; o[3*j+2] = Gz[j];
            }
        }
    }
}

extern "C" void kernel_launch(void* const* d_in, const int* in_sizes, int n_in,
                              void* d_out, int out_size)
{
    const float4* pos = (const float4*)d_in[1];
    const float4* rot = (const float4*)d_in[2];
    float4* out = (float4*)d_out;

    static int grid = 0;
    if (!grid) {
        cudaFuncSetAttribute(fk_kernel, cudaFuncAttributePreferredSharedMemoryCarveout, 100);
        int dev = 0, sms = 148;
        cudaGetDevice(&dev);
        cudaDeviceGetAttribute(&sms, cudaDevAttrMultiProcessorCount, dev);
        grid = 10 * sms;                 // exactly 10 persistent pipelines per SM
    }

    int nB = in_sizes[1] / (NJ * 3);     // 131072
    int numTiles = nB / BB;              // 4096
    int g = grid < numTiles ? grid : numTiles;
    if (nB % BB) g = g < 1 ? 1 : g;      // ensure block 0 exists for remainder
    fk_kernel<<<g, T>>>(rot, pos, out, numTiles, nB);
}